// round 2
// baseline (speedup 1.0000x reference)
#include <cuda_runtime.h>
#include <cstdint>
#include <cstddef>

#define BB 16
#define NN 2048
#define CC 64
#define KK 20
#define OUTC 1024
#define CATC 192
#define NPTS (BB*NN)
#define EPSF 1e-5f

// ---------------- scratch (static __device__, no allocation) ----------------
__device__ float g_D[(size_t)BB*NN*NN];        // 268MB: neg_dist, reused per layer
__device__ int   g_idx[NPTS*KK];
__device__ float g_PQ[(size_t)NPTS*128];       // [P(64) | Q(64)] per point
__device__ float g_hmax[(size_t)NPTS*CC];
__device__ float g_hmin[(size_t)NPTS*CC];
__device__ float g_cat[(size_t)NPTS*CATC];     // f1|f2|f3
__device__ float g_xx[NPTS];
__device__ float g_s1[3][CC];
__device__ float g_s2[3][CC];
__device__ float g_s1f[OUTC];
__device__ float g_s2f[OUTC];
__device__ unsigned g_fmaxe[BB*OUTC];
__device__ unsigned g_fmine[BB*OUTC];

__device__ __forceinline__ float neg_inf(){ return __int_as_float(0xff800000); }
__device__ __forceinline__ unsigned encf(float f){
  unsigned u = __float_as_uint(f);
  return (u & 0x80000000u) ? ~u : (u | 0x80000000u);
}
__device__ __forceinline__ float decf(unsigned u){
  return __uint_as_float((u & 0x80000000u) ? (u ^ 0x80000000u) : ~u);
}

// ---------------- init ----------------
__global__ void k_init(){
  int i = blockIdx.x*256 + threadIdx.x;
  if (i < BB*OUTC){ g_fmaxe[i]=0u; g_fmine[i]=0xFFFFFFFFu; }
  if (i < OUTC){ g_s1f[i]=0.f; g_s2f[i]=0.f; }
  if (i < 3*CC){ (&g_s1[0][0])[i]=0.f; (&g_s2[0][0])[i]=0.f; }
}

// ---------------- squared norms of input x (4 points / 256-thr block) -------
__global__ void k_xx0(const float* __restrict__ x){
  int sub = threadIdx.x >> 6;
  int o   = threadIdx.x & 63;
  int p   = blockIdx.x*4 + sub;
  float v = x[(size_t)p*64 + o];
  float s = v*v;
  #pragma unroll
  for (int off=16; off; off>>=1) s += __shfl_down_sync(0xffffffffu, s, off);
  __shared__ float sm[8];
  if ((threadIdx.x & 31)==0) sm[threadIdx.x>>5] = s;
  __syncthreads();
  if (o==0) g_xx[p] = sm[sub*2] + sm[sub*2+1];
}

// ---------------- neg_dist tile GEMM: D = 2*F F^T - xx_n - xx_m -------------
__global__ void __launch_bounds__(256) k_dist(const float* __restrict__ xext,
                                              int useCat, int catOff, int ldf){
  const float* feat = useCat ? (g_cat + catOff) : xext;
  int b = blockIdx.z;
  int rb = blockIdx.y*64, cb = blockIdx.x*64;
  const float* Fb = feat + (size_t)b*NN*ldf;
  __shared__ float As[64][68];   // [k][m]
  __shared__ float Bs[64][68];
  int t = threadIdx.x;
  #pragma unroll
  for (int i=0;i<4;i++){
    int j = t + i*256;
    int m = j>>4, k4 = (j&15)*4;
    float4 a = *(const float4*)(Fb + (size_t)(rb+m)*ldf + k4);
    As[k4+0][m]=a.x; As[k4+1][m]=a.y; As[k4+2][m]=a.z; As[k4+3][m]=a.w;
    float4 c = *(const float4*)(Fb + (size_t)(cb+m)*ldf + k4);
    Bs[k4+0][m]=c.x; Bs[k4+1][m]=c.y; Bs[k4+2][m]=c.z; Bs[k4+3][m]=c.w;
  }
  __syncthreads();
  int ty=t>>4, tx=t&15;
  int m0=ty*4, n0=tx*4;
  float acc[4][4] = {};
  #pragma unroll 16
  for (int k=0;k<64;k++){
    float4 a4=*(const float4*)&As[k][m0];
    float4 b4=*(const float4*)&Bs[k][n0];
    float av[4]={a4.x,a4.y,a4.z,a4.w};
    float bv[4]={b4.x,b4.y,b4.z,b4.w};
    #pragma unroll
    for (int i=0;i<4;i++)
      #pragma unroll
      for (int j2=0;j2<4;j2++)
        acc[i][j2] += av[i]*bv[j2];
  }
  int grow = b*NN + rb + m0;
  int gcol = b*NN + cb + n0;
  float xr[4], xc[4];
  #pragma unroll
  for (int i=0;i<4;i++)  xr[i]=g_xx[grow+i];
  #pragma unroll
  for (int j2=0;j2<4;j2++) xc[j2]=g_xx[gcol+j2];
  #pragma unroll
  for (int i=0;i<4;i++){
    float4 o4;
    o4.x = 2.f*acc[i][0]-xr[i]-xc[0];
    o4.y = 2.f*acc[i][1]-xr[i]-xc[1];
    o4.z = 2.f*acc[i][2]-xr[i]-xc[2];
    o4.w = 2.f*acc[i][3]-xr[i]-xc[3];
    *(float4*)&g_D[(size_t)(grow+i)*NN + cb + n0] = o4;
  }
}

// ---------------- top-20 per row (warp/row; tie-break lower index) ----------
__device__ __forceinline__ bool better(float av,int ai,float bv,int bi){
  return (av>bv) || (av==bv && ai<bi);
}

__global__ void __launch_bounds__(128) k_topk(){
  int w = threadIdx.x>>5, lane = threadIdx.x&31;
  int row = blockIdx.x*4 + w;
  const float4* drow = (const float4*)(g_D + (size_t)row*NN);
  float v[KK]; int id[KK];
  #pragma unroll
  for (int i=0;i<KK;i++){ v[i]=neg_inf(); id[i]=0x7fffffff; }
  int worst=0; float wv=neg_inf(); int wi=0x7fffffff;
  for (int i=0;i<16;i++){
    float4 d = drow[i*32+lane];
    int c = (i*32+lane)*4;
    float dv[4]={d.x,d.y,d.z,d.w};
    #pragma unroll
    for (int q=0;q<4;q++){
      if (better(dv[q], c+q, wv, wi)){
        v[worst]=dv[q]; id[worst]=c+q;
        worst=0; wv=v[0]; wi=id[0];
        #pragma unroll
        for (int j=1;j<KK;j++)
          if (better(wv, wi, v[j], id[j])){ worst=j; wv=v[j]; wi=id[j]; }
      }
    }
  }
  // insertion sort descending by (val desc, idx asc)
  for (int i=1;i<KK;i++){
    float kv=v[i]; int ki=id[i]; int j=i-1;
    for (; j>=0 && better(kv,ki,v[j],id[j]); j--){ v[j+1]=v[j]; id[j+1]=id[j]; }
    v[j+1]=kv; id[j+1]=ki;
  }
  // warp merge: 20 extract-max rounds
  int head=0;
  for (int r=0;r<KK;r++){
    float mv = (head<KK)? v[head] : neg_inf();
    int   mi = (head<KK)? id[head] : 0x7fffffff;
    float bv=mv; int bi=mi;
    #pragma unroll
    for (int off=16; off; off>>=1){
      float ov=__shfl_xor_sync(0xffffffffu,bv,off);
      int   oi=__shfl_xor_sync(0xffffffffu,bi,off);
      if (better(ov,oi,bv,bi)){ bv=ov; bi=oi; }
    }
    if (mi==bi && head<KK) head++;
    if (lane==0) g_idx[row*KK+r]=bi;
  }
}

// ---------------- P/Q projection -------------------------------------------
__global__ void __launch_bounds__(256) k_pq(const float* __restrict__ xext,
                                            int useCat, int catOff, int ldf,
                                            const float* __restrict__ W){
  const float* feat = useCat ? (g_cat + catOff) : xext;
  __shared__ float Fs[64][64];    // [m][k]
  __shared__ float Ws[64][128];   // [k][j]
  int t = threadIdx.x;
  int mb = blockIdx.x*64;
  #pragma unroll
  for (int i=0;i<4;i++){
    int j = t + i*256;
    int m = j>>4, k4=(j&15)*4;
    float4 a = *(const float4*)(feat + (size_t)(mb+m)*ldf + k4);
    *(float4*)&Fs[m][k4] = a;
  }
  #pragma unroll
  for (int i=0;i<32;i++){
    int l = t + i*256;
    int k = l>>7, j = l&127;
    Ws[k][j] = (j<64)? W[j*128 + k] : W[(j-64)*128 + 64 + k];
  }
  __syncthreads();
  int ty=t>>4, tx=t&15;
  int m0=ty*4, o0=tx*8;
  float acc[4][8] = {};
  #pragma unroll 8
  for (int k=0;k<64;k++){
    float av[4];
    #pragma unroll
    for (int i=0;i<4;i++) av[i]=Fs[m0+i][k];
    float4 w0=*(const float4*)&Ws[k][o0];
    float4 w1=*(const float4*)&Ws[k][o0+4];
    float wv[8]={w0.x,w0.y,w0.z,w0.w,w1.x,w1.y,w1.z,w1.w};
    #pragma unroll
    for (int i=0;i<4;i++)
      #pragma unroll
      for (int j2=0;j2<8;j2++)
        acc[i][j2] += av[i]*wv[j2];
  }
  #pragma unroll
  for (int i=0;i<4;i++){
    float* dst = g_PQ + (size_t)(mb+m0+i)*128 + o0;
    float4 u,vv;
    u.x=acc[i][0]; u.y=acc[i][1]; u.z=acc[i][2]; u.w=acc[i][3];
    vv.x=acc[i][4]; vv.y=acc[i][5]; vv.z=acc[i][6]; vv.w=acc[i][7];
    *(float4*)dst = u;
    *(float4*)(dst+4) = vv;
  }
}

// -------- gather: h = P[m] + (Q[n]-P[n]); max/min over k + channel stats ----
__global__ void __launch_bounds__(256) k_gather(int layer){
  __shared__ float ss1[64], ss2[64];
  int t = threadIdx.x;
  if (t<64){ ss1[t]=0.f; ss2[t]=0.f; }
  __syncthreads();
  int w=t>>5, lane=t&31;
  float ls1a=0.f, ls1b=0.f, ls2a=0.f, ls2b=0.f;
  for (int p=0;p<8;p++){
    int point = blockIdx.x*64 + w*8 + p;
    int b = point >> 11;
    const float* pqn = g_PQ + (size_t)point*128;
    float ra  = pqn[64+lane] - pqn[lane];
    float rb2 = pqn[96+lane] - pqn[32+lane];
    float hxa=neg_inf(), hxb=neg_inf();
    float hna=-neg_inf(), hnb=-neg_inf();
    const int* ids = g_idx + point*KK;
    #pragma unroll 4
    for (int k=0;k<KK;k++){
      int m = ids[k];
      const float* pm = g_PQ + (size_t)((b<<11)+m)*128;
      float ha = pm[lane]    + ra;
      float hb = pm[32+lane] + rb2;
      ls1a+=ha; ls2a+=ha*ha; hxa=fmaxf(hxa,ha); hna=fminf(hna,ha);
      ls1b+=hb; ls2b+=hb*hb; hxb=fmaxf(hxb,hb); hnb=fminf(hnb,hb);
    }
    g_hmax[(size_t)point*64+lane]=hxa; g_hmax[(size_t)point*64+32+lane]=hxb;
    g_hmin[(size_t)point*64+lane]=hna; g_hmin[(size_t)point*64+32+lane]=hnb;
  }
  atomicAdd(&ss1[lane],    ls1a); atomicAdd(&ss1[lane+32], ls1b);
  atomicAdd(&ss2[lane],    ls2a); atomicAdd(&ss2[lane+32], ls2b);
  __syncthreads();
  if (t<64){ atomicAdd(&g_s1[layer][t], ss1[t]); atomicAdd(&g_s2[layer][t], ss2[t]); }
}

// -------- finalize edge layer: BN+lrelu (max-over-k done) -> cat, xx --------
__global__ void k_efinal(int layer, const float* __restrict__ gg,
                         const float* __restrict__ bbv, int catOff){
  int sub = threadIdx.x>>6;
  int o   = threadIdx.x & 63;
  int p   = blockIdx.x*4 + sub;
  const float cnt = (float)NPTS * (float)KK;
  float mean = g_s1[layer][o]/cnt;
  float var  = g_s2[layer][o]/cnt - mean*mean;
  float scale = rsqrtf(var + EPSF) * gg[o];
  float shift = bbv[o] - mean*scale;
  float h = (scale>=0.f)? g_hmax[(size_t)p*64+o] : g_hmin[(size_t)p*64+o];
  float y = h*scale + shift;
  y = (y>=0.f)? y : 0.2f*y;
  g_cat[(size_t)p*CATC + catOff + o] = y;
  float s = y*y;
  #pragma unroll
  for (int off=16; off; off>>=1) s += __shfl_down_sync(0xffffffffu, s, off);
  __shared__ float sm[8];
  if ((threadIdx.x&31)==0) sm[threadIdx.x>>5]=s;
  __syncthreads();
  if (o==0) g_xx[p] = sm[sub*2]+sm[sub*2+1];
}

// -------- final GEMM cat[32768x192] @ Wf^T, streaming stats epilogue --------
__global__ void __launch_bounds__(256) k_fgemm(const float* __restrict__ Wf){
  __shared__ float Fs[64][64];     // reused as red[2][16][128] in epilogue
  __shared__ float Ws[64][128];
  int t = threadIdx.x;
  int rb = blockIdx.x*64;
  int ob = blockIdx.y*128;
  int b  = rb >> 11;
  int ty=t>>4, tx=t&15;
  int m0=ty*4, o0=tx*8;
  float acc[4][8] = {};
  for (int kc=0;kc<3;kc++){
    __syncthreads();
    #pragma unroll
    for (int i=0;i<4;i++){
      int j = t + i*256;
      int m = j>>4, k4=(j&15)*4;
      float4 a = *(const float4*)(g_cat + (size_t)(rb+m)*CATC + kc*64 + k4);
      *(float4*)&Fs[m][k4] = a;
    }
    #pragma unroll
    for (int i=0;i<32;i++){
      int l = t + i*256;
      int k = l>>7, j = l&127;
      Ws[k][j] = Wf[(size_t)(ob+j)*CATC + kc*64 + k];
    }
    __syncthreads();
    #pragma unroll 8
    for (int k=0;k<64;k++){
      float av[4];
      #pragma unroll
      for (int i=0;i<4;i++) av[i]=Fs[m0+i][k];
      float4 w0=*(const float4*)&Ws[k][o0];
      float4 w1=*(const float4*)&Ws[k][o0+4];
      float wv[8]={w0.x,w0.y,w0.z,w0.w,w1.x,w1.y,w1.z,w1.w};
      #pragma unroll
      for (int i=0;i<4;i++)
        #pragma unroll
        for (int j2=0;j2<8;j2++)
          acc[i][j2] += av[i]*wv[j2];
    }
  }
  __syncthreads();
  float* red = &Fs[0][0];          // 4096 floats: two [16][128] halves
  // pass A: max + min
  #pragma unroll
  for (int j2=0;j2<8;j2++){
    red[      ty*128 + o0 + j2] = fmaxf(fmaxf(acc[0][j2],acc[1][j2]),
                                        fmaxf(acc[2][j2],acc[3][j2]));
    red[2048 + ty*128 + o0 + j2] = fminf(fminf(acc[0][j2],acc[1][j2]),
                                        fminf(acc[2][j2],acc[3][j2]));
  }
  __syncthreads();
  if (t < 128){
    float mx = neg_inf(), mn = -neg_inf();
    #pragma unroll
    for (int r=0;r<16;r++){
      mx = fmaxf(mx, red[r*128+t]);
      mn = fminf(mn, red[2048+r*128+t]);
    }
    atomicMax(&g_fmaxe[b*OUTC + ob + t], encf(mx));
    atomicMin(&g_fmine[b*OUTC + ob + t], encf(mn));
  }
  __syncthreads();
  // pass B: sum + sumsq
  #pragma unroll
  for (int j2=0;j2<8;j2++){
    float s = acc[0][j2]+acc[1][j2]+acc[2][j2]+acc[3][j2];
    float q = acc[0][j2]*acc[0][j2]+acc[1][j2]*acc[1][j2]
            + acc[2][j2]*acc[2][j2]+acc[3][j2]*acc[3][j2];
    red[      ty*128 + o0 + j2] = s;
    red[2048 + ty*128 + o0 + j2] = q;
  }
  __syncthreads();
  if (t < 128){
    float s=0.f, q=0.f;
    #pragma unroll
    for (int r=0;r<16;r++){ s += red[r*128+t]; q += red[2048+r*128+t]; }
    atomicAdd(&g_s1f[ob + t], s);
    atomicAdd(&g_s2f[ob + t], q);
  }
}

// -------- final BN + lrelu + pick max/min ----------------------------------
__global__ void k_fout(const float* __restrict__ gf, const float* __restrict__ bf,
                       float* __restrict__ out){
  int i = blockIdx.x*256 + threadIdx.x;   // 0..16383
  int o = i & (OUTC-1);
  const float cnt = (float)NPTS;
  float mean = g_s1f[o]/cnt;
  float var  = g_s2f[o]/cnt - mean*mean;
  float scale = rsqrtf(var + EPSF) * gf[o];
  float shift = bf[o] - mean*scale;
  float h = (scale>=0.f)? decf(g_fmaxe[i]) : decf(g_fmine[i]);
  float y = h*scale + shift;
  out[i] = (y>=0.f)? y : 0.2f*y;
}

extern "C" void kernel_launch(void* const* d_in, const int* in_sizes, int n_in,
                              void* d_out, int out_size){
  const float* x   = (const float*)d_in[0];
  const float* W[3]  = {(const float*)d_in[1],(const float*)d_in[4],(const float*)d_in[7]};
  const float* G[3]  = {(const float*)d_in[2],(const float*)d_in[5],(const float*)d_in[8]};
  const float* Bv[3] = {(const float*)d_in[3],(const float*)d_in[6],(const float*)d_in[9]};
  const float* Wf = (const float*)d_in[10];
  const float* gf = (const float*)d_in[11];
  const float* bf = (const float*)d_in[12];
  float* out = (float*)d_out;

  k_init<<<64,256>>>();
  k_xx0<<<NPTS/4,256>>>(x);
  for (int l=0;l<3;l++){
    int useCat = (l>0);
    int catOff = useCat ? (l-1)*64 : 0;
    int ldf    = useCat ? CATC : CC;
    k_dist <<<dim3(NN/64, NN/64, BB),256>>>(x, useCat, catOff, ldf);
    k_topk <<<NPTS/4,128>>>();
    k_pq   <<<NPTS/64,256>>>(x, useCat, catOff, ldf, W[l]);
    k_gather<<<NPTS/64,256>>>(l);
    k_efinal<<<NPTS/4,256>>>(l, G[l], Bv[l], l*64);
  }
  k_fgemm<<<dim3(NPTS/64, OUTC/128),256>>>(Wf);
  k_fout <<<BB*OUTC/256,256>>>(gf, bf, out);
}

// round 3
// speedup vs baseline: 1.5563x; 1.5563x over previous
#include <cuda_runtime.h>
#include <cstdint>
#include <cstddef>

#define BB 16
#define NN 2048
#define CC 64
#define KK 20
#define OUTC 1024
#define CATC 192
#define NPTS (BB*NN)
#define EPSF 1e-5f

// ---------------- scratch (static __device__, no allocation) ----------------
__device__ float g_D[(size_t)BB*NN*NN];        // 268MB: neg_dist, reused per layer
__device__ int   g_idx[NPTS*KK];
__device__ float g_PQ[(size_t)NPTS*128];       // [P(64) | Q(64)] per point
__device__ float g_hmax[(size_t)NPTS*CC];
__device__ float g_hmin[(size_t)NPTS*CC];
__device__ float g_cat[(size_t)NPTS*CATC];     // f1|f2|f3
__device__ float g_xx[NPTS];
__device__ float g_s1[3][CC];
__device__ float g_s2[3][CC];
__device__ float g_s1f[OUTC];
__device__ float g_s2f[OUTC];
__device__ unsigned g_fmaxe[BB*OUTC];
__device__ unsigned g_fmine[BB*OUTC];

__device__ __forceinline__ float neg_inf(){ return __int_as_float(0xff800000); }
__device__ __forceinline__ unsigned encf(float f){
  unsigned u = __float_as_uint(f);
  return (u & 0x80000000u) ? ~u : (u | 0x80000000u);
}
__device__ __forceinline__ float decf(unsigned u){
  return __uint_as_float((u & 0x80000000u) ? (u ^ 0x80000000u) : ~u);
}

// ---------------- init ----------------
__global__ void k_init(){
  int i = blockIdx.x*256 + threadIdx.x;
  if (i < BB*OUTC){ g_fmaxe[i]=0u; g_fmine[i]=0xFFFFFFFFu; }
  if (i < OUTC){ g_s1f[i]=0.f; g_s2f[i]=0.f; }
  if (i < 3*CC){ (&g_s1[0][0])[i]=0.f; (&g_s2[0][0])[i]=0.f; }
}

// ---------------- squared norms of input x (4 points / 256-thr block) -------
__global__ void k_xx0(const float* __restrict__ x){
  int sub = threadIdx.x >> 6;
  int o   = threadIdx.x & 63;
  int p   = blockIdx.x*4 + sub;
  float v = x[(size_t)p*64 + o];
  float s = v*v;
  #pragma unroll
  for (int off=16; off; off>>=1) s += __shfl_down_sync(0xffffffffu, s, off);
  __shared__ float sm[8];
  if ((threadIdx.x & 31)==0) sm[threadIdx.x>>5] = s;
  __syncthreads();
  if (o==0) g_xx[p] = sm[sub*2] + sm[sub*2+1];
}

// ---------------- neg_dist tile GEMM: D = 2*F F^T - xx_n - xx_m -------------
__global__ void __launch_bounds__(256) k_dist(const float* __restrict__ xext,
                                              int useCat, int catOff, int ldf){
  const float* feat = useCat ? (g_cat + catOff) : xext;
  int b = blockIdx.z;
  int rb = blockIdx.y*64, cb = blockIdx.x*64;
  const float* Fb = feat + (size_t)b*NN*ldf;
  __shared__ float As[64][68];   // [k][m]
  __shared__ float Bs[64][68];
  int t = threadIdx.x;
  #pragma unroll
  for (int i=0;i<4;i++){
    int j = t + i*256;
    int m = j>>4, k4 = (j&15)*4;
    float4 a = *(const float4*)(Fb + (size_t)(rb+m)*ldf + k4);
    As[k4+0][m]=a.x; As[k4+1][m]=a.y; As[k4+2][m]=a.z; As[k4+3][m]=a.w;
    float4 c = *(const float4*)(Fb + (size_t)(cb+m)*ldf + k4);
    Bs[k4+0][m]=c.x; Bs[k4+1][m]=c.y; Bs[k4+2][m]=c.z; Bs[k4+3][m]=c.w;
  }
  __syncthreads();
  int ty=t>>4, tx=t&15;
  int m0=ty*4, n0=tx*4;
  float acc[4][4] = {};
  #pragma unroll 16
  for (int k=0;k<64;k++){
    float4 a4=*(const float4*)&As[k][m0];
    float4 b4=*(const float4*)&Bs[k][n0];
    float av[4]={a4.x,a4.y,a4.z,a4.w};
    float bv[4]={b4.x,b4.y,b4.z,b4.w};
    #pragma unroll
    for (int i=0;i<4;i++)
      #pragma unroll
      for (int j2=0;j2<4;j2++)
        acc[i][j2] += av[i]*bv[j2];
  }
  int grow = b*NN + rb + m0;
  int gcol = b*NN + cb + n0;
  float xr[4], xc[4];
  #pragma unroll
  for (int i=0;i<4;i++)  xr[i]=g_xx[grow+i];
  #pragma unroll
  for (int j2=0;j2<4;j2++) xc[j2]=g_xx[gcol+j2];
  #pragma unroll
  for (int i=0;i<4;i++){
    float4 o4;
    o4.x = 2.f*acc[i][0]-xr[i]-xc[0];
    o4.y = 2.f*acc[i][1]-xr[i]-xc[1];
    o4.z = 2.f*acc[i][2]-xr[i]-xc[2];
    o4.w = 2.f*acc[i][3]-xr[i]-xc[3];
    *(float4*)&g_D[(size_t)(grow+i)*NN + cb + n0] = o4;
  }
}

// ---------------- warp-bitonic top-20 per row ------------------------------
__device__ __forceinline__ bool better(float av,int ai,float bv,int bi){
  return (av>bv) || (av==bv && ai<bi);
}

// compare-exchange with partner lane^j; keep smaller if wantSmaller
__device__ __forceinline__ void cmpswap(float& v, int& i, int j, bool wantSmaller){
  float ov = __shfl_xor_sync(0xffffffffu, v, j);
  int   oi = __shfl_xor_sync(0xffffffffu, i, j);
  bool ob = better(ov, oi, v, i);
  if (ob != wantSmaller){ v = ov; i = oi; }
}

__global__ void __launch_bounds__(256) k_topk(){
  int w = threadIdx.x>>5, lane = threadIdx.x&31;
  int row = blockIdx.x*8 + w;
  const float* drow = g_D + (size_t)row*NN;

  // R across lanes, sorted descending by (val desc, idx asc)
  float rv = neg_inf(); int ri = 0x7fffffff;
  float thr = neg_inf(); int thri = 0x7fffffff;   // current 20th best

  for (int b=0; b<64; b++){
    int   i = b*32 + lane;
    float v = __ldg(&drow[i]);
    // prune: skip batch if nothing beats the current 20th best
    if (!__ballot_sync(0xffffffffu, better(v, i, thr, thri))) continue;

    // bitonic sort batch ascending (worst at lane 0)
    #pragma unroll
    for (int k=2; k<=32; k<<=1){
      #pragma unroll
      for (int j=k>>1; j; j>>=1){
        bool up = ((lane & k) == 0);
        bool wantSmaller = (((lane & j) == 0) == up);
        cmpswap(v, i, j, wantSmaller);
      }
    }
    // elementwise max of (R desc, B asc) = top-32 of union, bitonic
    if (better(v, i, rv, ri)){ rv = v; ri = i; }
    // bitonic merge to descending
    #pragma unroll
    for (int j=16; j; j>>=1){
      bool wantSmaller = ((lane & j) != 0);
      cmpswap(rv, ri, j, wantSmaller);
    }
    thr  = __shfl_sync(0xffffffffu, rv, 19);
    thri = __shfl_sync(0xffffffffu, ri, 19);
  }
  if (lane < KK) g_idx[row*KK + lane] = ri;
}

// ---------------- P/Q projection -------------------------------------------
__global__ void __launch_bounds__(256) k_pq(const float* __restrict__ xext,
                                            int useCat, int catOff, int ldf,
                                            const float* __restrict__ W){
  const float* feat = useCat ? (g_cat + catOff) : xext;
  __shared__ float Fs[64][64];    // [m][k]
  __shared__ float Ws[64][128];   // [k][j]
  int t = threadIdx.x;
  int mb = blockIdx.x*64;
  #pragma unroll
  for (int i=0;i<4;i++){
    int j = t + i*256;
    int m = j>>4, k4=(j&15)*4;
    float4 a = *(const float4*)(feat + (size_t)(mb+m)*ldf + k4);
    *(float4*)&Fs[m][k4] = a;
  }
  #pragma unroll
  for (int i=0;i<32;i++){
    int l = t + i*256;
    int k = l>>7, j = l&127;
    Ws[k][j] = (j<64)? W[j*128 + k] : W[(j-64)*128 + 64 + k];
  }
  __syncthreads();
  int ty=t>>4, tx=t&15;
  int m0=ty*4, o0=tx*8;
  float acc[4][8] = {};
  #pragma unroll 8
  for (int k=0;k<64;k++){
    float av[4];
    #pragma unroll
    for (int i=0;i<4;i++) av[i]=Fs[m0+i][k];
    float4 w0=*(const float4*)&Ws[k][o0];
    float4 w1=*(const float4*)&Ws[k][o0+4];
    float wv[8]={w0.x,w0.y,w0.z,w0.w,w1.x,w1.y,w1.z,w1.w};
    #pragma unroll
    for (int i=0;i<4;i++)
      #pragma unroll
      for (int j2=0;j2<8;j2++)
        acc[i][j2] += av[i]*wv[j2];
  }
  #pragma unroll
  for (int i=0;i<4;i++){
    float* dst = g_PQ + (size_t)(mb+m0+i)*128 + o0;
    float4 u,vv;
    u.x=acc[i][0]; u.y=acc[i][1]; u.z=acc[i][2]; u.w=acc[i][3];
    vv.x=acc[i][4]; vv.y=acc[i][5]; vv.z=acc[i][6]; vv.w=acc[i][7];
    *(float4*)dst = u;
    *(float4*)(dst+4) = vv;
  }
}

// -------- gather: h = P[m] + (Q[n]-P[n]); max/min over k + channel stats ----
__global__ void __launch_bounds__(256) k_gather(int layer){
  __shared__ float ss1[64], ss2[64];
  int t = threadIdx.x;
  if (t<64){ ss1[t]=0.f; ss2[t]=0.f; }
  __syncthreads();
  int w=t>>5, lane=t&31;
  float ls1a=0.f, ls1b=0.f, ls2a=0.f, ls2b=0.f;
  for (int p=0;p<8;p++){
    int point = blockIdx.x*64 + w*8 + p;
    int b = point >> 11;
    const float* pqn = g_PQ + (size_t)point*128;
    float ra  = pqn[64+lane] - pqn[lane];
    float rb2 = pqn[96+lane] - pqn[32+lane];
    float hxa=neg_inf(), hxb=neg_inf();
    float hna=-neg_inf(), hnb=-neg_inf();
    const int* ids = g_idx + point*KK;
    #pragma unroll 4
    for (int k=0;k<KK;k++){
      int m = ids[k];
      const float* pm = g_PQ + (size_t)((b<<11)+m)*128;
      float ha = pm[lane]    + ra;
      float hb = pm[32+lane] + rb2;
      ls1a+=ha; ls2a+=ha*ha; hxa=fmaxf(hxa,ha); hna=fminf(hna,ha);
      ls1b+=hb; ls2b+=hb*hb; hxb=fmaxf(hxb,hb); hnb=fminf(hnb,hb);
    }
    g_hmax[(size_t)point*64+lane]=hxa; g_hmax[(size_t)point*64+32+lane]=hxb;
    g_hmin[(size_t)point*64+lane]=hna; g_hmin[(size_t)point*64+32+lane]=hnb;
  }
  atomicAdd(&ss1[lane],    ls1a); atomicAdd(&ss1[lane+32], ls1b);
  atomicAdd(&ss2[lane],    ls2a); atomicAdd(&ss2[lane+32], ls2b);
  __syncthreads();
  if (t<64){ atomicAdd(&g_s1[layer][t], ss1[t]); atomicAdd(&g_s2[layer][t], ss2[t]); }
}

// -------- finalize edge layer: BN+lrelu (max-over-k done) -> cat, xx --------
__global__ void k_efinal(int layer, const float* __restrict__ gg,
                         const float* __restrict__ bbv, int catOff){
  int sub = threadIdx.x>>6;
  int o   = threadIdx.x & 63;
  int p   = blockIdx.x*4 + sub;
  const float cnt = (float)NPTS * (float)KK;
  float mean = g_s1[layer][o]/cnt;
  float var  = g_s2[layer][o]/cnt - mean*mean;
  float scale = rsqrtf(var + EPSF) * gg[o];
  float shift = bbv[o] - mean*scale;
  float h = (scale>=0.f)? g_hmax[(size_t)p*64+o] : g_hmin[(size_t)p*64+o];
  float y = h*scale + shift;
  y = (y>=0.f)? y : 0.2f*y;
  g_cat[(size_t)p*CATC + catOff + o] = y;
  float s = y*y;
  #pragma unroll
  for (int off=16; off; off>>=1) s += __shfl_down_sync(0xffffffffu, s, off);
  __shared__ float sm[8];
  if ((threadIdx.x&31)==0) sm[threadIdx.x>>5]=s;
  __syncthreads();
  if (o==0) g_xx[p] = sm[sub*2]+sm[sub*2+1];
}

// -------- final GEMM cat[32768x192] @ Wf^T, streaming stats epilogue --------
__global__ void __launch_bounds__(256) k_fgemm(const float* __restrict__ Wf){
  __shared__ float Fs[64][64];     // reused as red[2][16][128] in epilogue
  __shared__ float Ws[64][128];
  int t = threadIdx.x;
  int rb = blockIdx.x*64;
  int ob = blockIdx.y*128;
  int b  = rb >> 11;
  int ty=t>>4, tx=t&15;
  int m0=ty*4, o0=tx*8;
  float acc[4][8] = {};
  for (int kc=0;kc<3;kc++){
    __syncthreads();
    #pragma unroll
    for (int i=0;i<4;i++){
      int j = t + i*256;
      int m = j>>4, k4=(j&15)*4;
      float4 a = *(const float4*)(g_cat + (size_t)(rb+m)*CATC + kc*64 + k4);
      *(float4*)&Fs[m][k4] = a;
    }
    #pragma unroll
    for (int i=0;i<32;i++){
      int l = t + i*256;
      int k = l>>7, j = l&127;
      Ws[k][j] = Wf[(size_t)(ob+j)*CATC + kc*64 + k];
    }
    __syncthreads();
    #pragma unroll 8
    for (int k=0;k<64;k++){
      float av[4];
      #pragma unroll
      for (int i=0;i<4;i++) av[i]=Fs[m0+i][k];
      float4 w0=*(const float4*)&Ws[k][o0];
      float4 w1=*(const float4*)&Ws[k][o0+4];
      float wv[8]={w0.x,w0.y,w0.z,w0.w,w1.x,w1.y,w1.z,w1.w};
      #pragma unroll
      for (int i=0;i<4;i++)
        #pragma unroll
        for (int j2=0;j2<8;j2++)
          acc[i][j2] += av[i]*wv[j2];
    }
  }
  __syncthreads();
  float* red = &Fs[0][0];          // 4096 floats: two [16][128] halves
  #pragma unroll
  for (int j2=0;j2<8;j2++){
    red[      ty*128 + o0 + j2] = fmaxf(fmaxf(acc[0][j2],acc[1][j2]),
                                        fmaxf(acc[2][j2],acc[3][j2]));
    red[2048 + ty*128 + o0 + j2] = fminf(fminf(acc[0][j2],acc[1][j2]),
                                        fminf(acc[2][j2],acc[3][j2]));
  }
  __syncthreads();
  if (t < 128){
    float mx = neg_inf(), mn = -neg_inf();
    #pragma unroll
    for (int r=0;r<16;r++){
      mx = fmaxf(mx, red[r*128+t]);
      mn = fminf(mn, red[2048+r*128+t]);
    }
    atomicMax(&g_fmaxe[b*OUTC + ob + t], encf(mx));
    atomicMin(&g_fmine[b*OUTC + ob + t], encf(mn));
  }
  __syncthreads();
  #pragma unroll
  for (int j2=0;j2<8;j2++){
    float s = acc[0][j2]+acc[1][j2]+acc[2][j2]+acc[3][j2];
    float q = acc[0][j2]*acc[0][j2]+acc[1][j2]*acc[1][j2]
            + acc[2][j2]*acc[2][j2]+acc[3][j2]*acc[3][j2];
    red[      ty*128 + o0 + j2] = s;
    red[2048 + ty*128 + o0 + j2] = q;
  }
  __syncthreads();
  if (t < 128){
    float s=0.f, q=0.f;
    #pragma unroll
    for (int r=0;r<16;r++){ s += red[r*128+t]; q += red[2048+r*128+t]; }
    atomicAdd(&g_s1f[ob + t], s);
    atomicAdd(&g_s2f[ob + t], q);
  }
}

// -------- final BN + lrelu + pick max/min ----------------------------------
__global__ void k_fout(const float* __restrict__ gf, const float* __restrict__ bf,
                       float* __restrict__ out){
  int i = blockIdx.x*256 + threadIdx.x;   // 0..16383
  int o = i & (OUTC-1);
  const float cnt = (float)NPTS;
  float mean = g_s1f[o]/cnt;
  float var  = g_s2f[o]/cnt - mean*mean;
  float scale = rsqrtf(var + EPSF) * gf[o];
  float shift = bf[o] - mean*scale;
  float h = (scale>=0.f)? decf(g_fmaxe[i]) : decf(g_fmine[i]);
  float y = h*scale + shift;
  out[i] = (y>=0.f)? y : 0.2f*y;
}

extern "C" void kernel_launch(void* const* d_in, const int* in_sizes, int n_in,
                              void* d_out, int out_size){
  const float* x   = (const float*)d_in[0];
  const float* W[3]  = {(const float*)d_in[1],(const float*)d_in[4],(const float*)d_in[7]};
  const float* G[3]  = {(const float*)d_in[2],(const float*)d_in[5],(const float*)d_in[8]};
  const float* Bv[3] = {(const float*)d_in[3],(const float*)d_in[6],(const float*)d_in[9]};
  const float* Wf = (const float*)d_in[10];
  const float* gf = (const float*)d_in[11];
  const float* bf = (const float*)d_in[12];
  float* out = (float*)d_out;

  k_init<<<64,256>>>();
  k_xx0<<<NPTS/4,256>>>(x);
  for (int l=0;l<3;l++){
    int useCat = (l>0);
    int catOff = useCat ? (l-1)*64 : 0;
    int ldf    = useCat ? CATC : CC;
    k_dist <<<dim3(NN/64, NN/64, BB),256>>>(x, useCat, catOff, ldf);
    k_topk <<<NPTS/8,256>>>();
    k_pq   <<<NPTS/64,256>>>(x, useCat, catOff, ldf, W[l]);
    k_gather<<<NPTS/64,256>>>(l);
    k_efinal<<<NPTS/4,256>>>(l, G[l], Bv[l], l*64);
  }
  k_fgemm<<<dim3(NPTS/64, OUTC/128),256>>>(Wf);
  k_fout <<<BB*OUTC/256,256>>>(gf, bf, out);
}

// round 4
// speedup vs baseline: 2.2685x; 1.4577x over previous
#include <cuda_runtime.h>
#include <cstdint>
#include <cstddef>

#define BB 16
#define NN 2048
#define CC 64
#define KK 20
#define OUTC 1024
#define CATC 192
#define NPTS (BB*NN)
#define EPSF 1e-5f

// ---------------- scratch (static __device__, no allocation) ----------------
__device__ float g_D[(size_t)BB*NN*NN];        // 268MB: neg_dist, reused per layer
__device__ int   g_idx[NPTS*KK];
__device__ float g_PQ[(size_t)NPTS*128];       // [P(64) | Q(64)] per point
__device__ float g_hmax[(size_t)NPTS*CC];
__device__ float g_hmin[(size_t)NPTS*CC];
__device__ float g_cat[(size_t)NPTS*CATC];     // f1|f2|f3
__device__ float g_xx[NPTS];
__device__ float g_s1[3][CC];
__device__ float g_s2[3][CC];
__device__ float g_s1f[OUTC];
__device__ float g_s2f[OUTC];
__device__ unsigned g_fmaxe[BB*OUTC];
__device__ unsigned g_fmine[BB*OUTC];

__device__ __forceinline__ float neg_inf(){ return __int_as_float(0xff800000); }
__device__ __forceinline__ unsigned encf(float f){
  unsigned u = __float_as_uint(f);
  return (u & 0x80000000u) ? ~u : (u | 0x80000000u);
}
__device__ __forceinline__ float decf(unsigned u){
  return __uint_as_float((u & 0x80000000u) ? (u ^ 0x80000000u) : ~u);
}

// ---------------- init ----------------
__global__ void k_init(){
  int i = blockIdx.x*256 + threadIdx.x;
  if (i < BB*OUTC){ g_fmaxe[i]=0u; g_fmine[i]=0xFFFFFFFFu; }
  if (i < OUTC){ g_s1f[i]=0.f; g_s2f[i]=0.f; }
  if (i < 3*CC){ (&g_s1[0][0])[i]=0.f; (&g_s2[0][0])[i]=0.f; }
}

// ---------------- squared norms of input x (4 points / 256-thr block) -------
__global__ void k_xx0(const float* __restrict__ x){
  int sub = threadIdx.x >> 6;
  int o   = threadIdx.x & 63;
  int p   = blockIdx.x*4 + sub;
  float v = x[(size_t)p*64 + o];
  float s = v*v;
  #pragma unroll
  for (int off=16; off; off>>=1) s += __shfl_down_sync(0xffffffffu, s, off);
  __shared__ float sm[8];
  if ((threadIdx.x & 31)==0) sm[threadIdx.x>>5] = s;
  __syncthreads();
  if (o==0) g_xx[p] = sm[sub*2] + sm[sub*2+1];
}

// ------- neg_dist GEMM: 128x128 tile, 8x8/thread, k chunked by 32 ----------
__global__ void __launch_bounds__(256) k_dist(const float* __restrict__ xext,
                                              int useCat, int catOff, int ldf){
  __shared__ float As[32][136];   // [k][m]
  __shared__ float Bs[32][136];   // [k][n]
  const float* feat = useCat ? (g_cat + catOff) : xext;
  int b = blockIdx.z;
  int rb = blockIdx.y*128, cb = blockIdx.x*128;
  const float* Fb = feat + (size_t)b*NN*ldf;
  int t = threadIdx.x;
  int ty = t>>4, tx = t&15;
  int m0 = ty*8, n0 = tx*8;
  float acc[8][8] = {};
  for (int kc=0; kc<2; kc++){
    __syncthreads();
    #pragma unroll
    for (int i=0;i<4;i++){
      int j = t + i*256;
      int m = j>>3, k4 = (j&7)*4;
      float4 a = *(const float4*)(Fb + (size_t)(rb+m)*ldf + kc*32 + k4);
      As[k4+0][m]=a.x; As[k4+1][m]=a.y; As[k4+2][m]=a.z; As[k4+3][m]=a.w;
      float4 c = *(const float4*)(Fb + (size_t)(cb+m)*ldf + kc*32 + k4);
      Bs[k4+0][m]=c.x; Bs[k4+1][m]=c.y; Bs[k4+2][m]=c.z; Bs[k4+3][m]=c.w;
    }
    __syncthreads();
    #pragma unroll 8
    for (int k=0;k<32;k++){
      float av[8], bv[8];
      *(float4*)&av[0] = *(const float4*)&As[k][m0];
      *(float4*)&av[4] = *(const float4*)&As[k][m0+4];
      *(float4*)&bv[0] = *(const float4*)&Bs[k][n0];
      *(float4*)&bv[4] = *(const float4*)&Bs[k][n0+4];
      #pragma unroll
      for (int i=0;i<8;i++)
        #pragma unroll
        for (int j2=0;j2<8;j2++)
          acc[i][j2] += av[i]*bv[j2];
    }
  }
  int grow = b*NN + rb + m0;
  int gcol = b*NN + cb + n0;
  float xr[8], xc[8];
  #pragma unroll
  for (int i=0;i<8;i++)  xr[i]=g_xx[grow+i];
  #pragma unroll
  for (int j2=0;j2<8;j2++) xc[j2]=g_xx[gcol+j2];
  #pragma unroll
  for (int i=0;i<8;i++){
    float4 o1,o2;
    o1.x=2.f*acc[i][0]-xr[i]-xc[0]; o1.y=2.f*acc[i][1]-xr[i]-xc[1];
    o1.z=2.f*acc[i][2]-xr[i]-xc[2]; o1.w=2.f*acc[i][3]-xr[i]-xc[3];
    o2.x=2.f*acc[i][4]-xr[i]-xc[4]; o2.y=2.f*acc[i][5]-xr[i]-xc[5];
    o2.z=2.f*acc[i][6]-xr[i]-xc[6]; o2.w=2.f*acc[i][7]-xr[i]-xc[7];
    float* dst = &g_D[(size_t)(grow+i)*NN + cb + n0];
    *(float4*)dst = o1; *(float4*)(dst+4) = o2;
  }
}

// ------- top-20 per row: packed u64 keys + warp insertion ------------------
// key = (encf(val) << 32) | ~idx  : larger key == better (val desc, idx asc)
__global__ void __launch_bounds__(256) k_topk(){
  int w = threadIdx.x>>5, lane = threadIdx.x&31;
  int row = blockIdx.x*8 + w;
  const float* drow = g_D + (size_t)row*NN;

  unsigned long long rk = 0ull;   // running top-32, sorted desc (lane0 best)
  unsigned long long thr = 0ull;  // key at rank 19 (20th best)

  for (int b=0; b<64; b++){
    int i = b*32 + lane;
    float v = __ldg(&drow[i]);
    unsigned long long key =
      ((unsigned long long)encf(v) << 32) | (unsigned)(~i);
    unsigned m = __ballot_sync(0xffffffffu, key > thr);
    while (m){
      int src = __ffs(m) - 1;
      unsigned long long ck = __shfl_sync(0xffffffffu, key, src);
      unsigned bet = __ballot_sync(0xffffffffu, rk > ck);
      int pos = __popc(bet);
      unsigned long long prev = __shfl_up_sync(0xffffffffu, rk, 1);
      if (lane == pos)      rk = ck;
      else if (lane > pos)  rk = prev;
      thr = __shfl_sync(0xffffffffu, rk, 19);
      if (lane == src) key = 0ull;
      m = __ballot_sync(0xffffffffu, key > thr);
    }
  }
  if (lane < KK) g_idx[row*KK + lane] = (int)(~(unsigned)(rk & 0xffffffffu));
}

// ---------------- P/Q projection -------------------------------------------
__global__ void __launch_bounds__(256) k_pq(const float* __restrict__ xext,
                                            int useCat, int catOff, int ldf,
                                            const float* __restrict__ W){
  const float* feat = useCat ? (g_cat + catOff) : xext;
  __shared__ float Fs[64][64];    // [m][k]
  __shared__ float Ws[64][128];   // [k][j]
  int t = threadIdx.x;
  int mb = blockIdx.x*64;
  #pragma unroll
  for (int i=0;i<4;i++){
    int j = t + i*256;
    int m = j>>4, k4=(j&15)*4;
    float4 a = *(const float4*)(feat + (size_t)(mb+m)*ldf + k4);
    *(float4*)&Fs[m][k4] = a;
  }
  #pragma unroll
  for (int i=0;i<32;i++){
    int l = t + i*256;
    int k = l>>7, j = l&127;
    Ws[k][j] = (j<64)? W[j*128 + k] : W[(j-64)*128 + 64 + k];
  }
  __syncthreads();
  int ty=t>>4, tx=t&15;
  int m0=ty*4, o0=tx*8;
  float acc[4][8] = {};
  #pragma unroll 8
  for (int k=0;k<64;k++){
    float av[4];
    #pragma unroll
    for (int i=0;i<4;i++) av[i]=Fs[m0+i][k];
    float4 w0=*(const float4*)&Ws[k][o0];
    float4 w1=*(const float4*)&Ws[k][o0+4];
    float wv[8]={w0.x,w0.y,w0.z,w0.w,w1.x,w1.y,w1.z,w1.w};
    #pragma unroll
    for (int i=0;i<4;i++)
      #pragma unroll
      for (int j2=0;j2<8;j2++)
        acc[i][j2] += av[i]*wv[j2];
  }
  #pragma unroll
  for (int i=0;i<4;i++){
    float* dst = g_PQ + (size_t)(mb+m0+i)*128 + o0;
    float4 u,vv;
    u.x=acc[i][0]; u.y=acc[i][1]; u.z=acc[i][2]; u.w=acc[i][3];
    vv.x=acc[i][4]; vv.y=acc[i][5]; vv.z=acc[i][6]; vv.w=acc[i][7];
    *(float4*)dst = u;
    *(float4*)(dst+4) = vv;
  }
}

// -------- gather: h = P[m] + (Q[n]-P[n]); max/min over k + channel stats ----
__global__ void __launch_bounds__(256) k_gather(int layer){
  __shared__ float ss1[64], ss2[64];
  int t = threadIdx.x;
  if (t<64){ ss1[t]=0.f; ss2[t]=0.f; }
  __syncthreads();
  int w=t>>5, lane=t&31;
  float ls1a=0.f, ls1b=0.f, ls2a=0.f, ls2b=0.f;
  for (int p=0;p<8;p++){
    int point = blockIdx.x*64 + w*8 + p;
    int b = point >> 11;
    const float* pqn = g_PQ + (size_t)point*128;
    float ra  = pqn[64+lane] - pqn[lane];
    float rb2 = pqn[96+lane] - pqn[32+lane];
    float hxa=neg_inf(), hxb=neg_inf();
    float hna=-neg_inf(), hnb=-neg_inf();
    const int* ids = g_idx + point*KK;
    #pragma unroll 4
    for (int k=0;k<KK;k++){
      int m = ids[k];
      const float* pm = g_PQ + (size_t)((b<<11)+m)*128;
      float ha = pm[lane]    + ra;
      float hb = pm[32+lane] + rb2;
      ls1a+=ha; ls2a+=ha*ha; hxa=fmaxf(hxa,ha); hna=fminf(hna,ha);
      ls1b+=hb; ls2b+=hb*hb; hxb=fmaxf(hxb,hb); hnb=fminf(hnb,hb);
    }
    g_hmax[(size_t)point*64+lane]=hxa; g_hmax[(size_t)point*64+32+lane]=hxb;
    g_hmin[(size_t)point*64+lane]=hna; g_hmin[(size_t)point*64+32+lane]=hnb;
  }
  atomicAdd(&ss1[lane],    ls1a); atomicAdd(&ss1[lane+32], ls1b);
  atomicAdd(&ss2[lane],    ls2a); atomicAdd(&ss2[lane+32], ls2b);
  __syncthreads();
  if (t<64){ atomicAdd(&g_s1[layer][t], ss1[t]); atomicAdd(&g_s2[layer][t], ss2[t]); }
}

// -------- finalize edge layer: BN+lrelu (max-over-k done) -> cat, xx --------
__global__ void k_efinal(int layer, const float* __restrict__ gg,
                         const float* __restrict__ bbv, int catOff){
  int sub = threadIdx.x>>6;
  int o   = threadIdx.x & 63;
  int p   = blockIdx.x*4 + sub;
  const float cnt = (float)NPTS * (float)KK;
  float mean = g_s1[layer][o]/cnt;
  float var  = g_s2[layer][o]/cnt - mean*mean;
  float scale = rsqrtf(var + EPSF) * gg[o];
  float shift = bbv[o] - mean*scale;
  float h = (scale>=0.f)? g_hmax[(size_t)p*64+o] : g_hmin[(size_t)p*64+o];
  float y = h*scale + shift;
  y = (y>=0.f)? y : 0.2f*y;
  g_cat[(size_t)p*CATC + catOff + o] = y;
  float s = y*y;
  #pragma unroll
  for (int off=16; off; off>>=1) s += __shfl_down_sync(0xffffffffu, s, off);
  __shared__ float sm[8];
  if ((threadIdx.x&31)==0) sm[threadIdx.x>>5]=s;
  __syncthreads();
  if (o==0) g_xx[p] = sm[sub*2]+sm[sub*2+1];
}

// -------- final GEMM: 128x128 tile, 8x8/thread, k chunked by 32 -------------
__global__ void __launch_bounds__(256) k_fgemm(const float* __restrict__ Wf){
  __shared__ float Fs[32][136];   // [k][m]
  __shared__ float Ws[32][136];   // [k][j]
  int t = threadIdx.x;
  int rb = blockIdx.x*128;
  int ob = blockIdx.y*128;
  int b  = rb >> 11;
  int ty=t>>4, tx=t&15;
  int m0=ty*8, o0=tx*8;
  float acc[8][8] = {};
  for (int kc=0;kc<6;kc++){
    __syncthreads();
    #pragma unroll
    for (int i=0;i<4;i++){
      int j = t + i*256;
      int m = j>>3, k4=(j&7)*4;
      float4 a = *(const float4*)(g_cat + (size_t)(rb+m)*CATC + kc*32 + k4);
      Fs[k4+0][m]=a.x; Fs[k4+1][m]=a.y; Fs[k4+2][m]=a.z; Fs[k4+3][m]=a.w;
    }
    #pragma unroll
    for (int i=0;i<16;i++){
      int l = t + i*256;
      int k = l>>7, j = l&127;
      Ws[k][j] = Wf[(size_t)(ob+j)*CATC + kc*32 + k];
    }
    __syncthreads();
    #pragma unroll 8
    for (int k=0;k<32;k++){
      float av[8], wv[8];
      *(float4*)&av[0] = *(const float4*)&Fs[k][m0];
      *(float4*)&av[4] = *(const float4*)&Fs[k][m0+4];
      *(float4*)&wv[0] = *(const float4*)&Ws[k][o0];
      *(float4*)&wv[4] = *(const float4*)&Ws[k][o0+4];
      #pragma unroll
      for (int i=0;i<8;i++)
        #pragma unroll
        for (int j2=0;j2<8;j2++)
          acc[i][j2] += av[i]*wv[j2];
    }
  }
  __syncthreads();
  float* red1 = &Fs[0][0];          // 16x128
  float* red2 = &Ws[0][0];          // 16x128
  // pass A: max + min over this block's 128 rows
  #pragma unroll
  for (int j2=0;j2<8;j2++){
    float mx = acc[0][j2], mn = acc[0][j2];
    #pragma unroll
    for (int i=1;i<8;i++){ mx = fmaxf(mx, acc[i][j2]); mn = fminf(mn, acc[i][j2]); }
    red1[ty*128 + o0 + j2] = mx;
    red2[ty*128 + o0 + j2] = mn;
  }
  __syncthreads();
  if (t < 128){
    float mx = neg_inf(), mn = -neg_inf();
    #pragma unroll
    for (int r=0;r<16;r++){
      mx = fmaxf(mx, red1[r*128+t]);
      mn = fminf(mn, red2[r*128+t]);
    }
    atomicMax(&g_fmaxe[b*OUTC + ob + t], encf(mx));
    atomicMin(&g_fmine[b*OUTC + ob + t], encf(mn));
  }
  __syncthreads();
  // pass B: sum + sumsq
  #pragma unroll
  for (int j2=0;j2<8;j2++){
    float s = 0.f, q = 0.f;
    #pragma unroll
    for (int i=0;i<8;i++){ s += acc[i][j2]; q += acc[i][j2]*acc[i][j2]; }
    red1[ty*128 + o0 + j2] = s;
    red2[ty*128 + o0 + j2] = q;
  }
  __syncthreads();
  if (t < 128){
    float s=0.f, q=0.f;
    #pragma unroll
    for (int r=0;r<16;r++){ s += red1[r*128+t]; q += red2[r*128+t]; }
    atomicAdd(&g_s1f[ob + t], s);
    atomicAdd(&g_s2f[ob + t], q);
  }
}

// -------- final BN + lrelu + pick max/min ----------------------------------
__global__ void k_fout(const float* __restrict__ gf, const float* __restrict__ bf,
                       float* __restrict__ out){
  int i = blockIdx.x*256 + threadIdx.x;   // 0..16383
  int o = i & (OUTC-1);
  const float cnt = (float)NPTS;
  float mean = g_s1f[o]/cnt;
  float var  = g_s2f[o]/cnt - mean*mean;
  float scale = rsqrtf(var + EPSF) * gf[o];
  float shift = bf[o] - mean*scale;
  float h = (scale>=0.f)? decf(g_fmaxe[i]) : decf(g_fmine[i]);
  float y = h*scale + shift;
  out[i] = (y>=0.f)? y : 0.2f*y;
}

extern "C" void kernel_launch(void* const* d_in, const int* in_sizes, int n_in,
                              void* d_out, int out_size){
  const float* x   = (const float*)d_in[0];
  const float* W[3]  = {(const float*)d_in[1],(const float*)d_in[4],(const float*)d_in[7]};
  const float* G[3]  = {(const float*)d_in[2],(const float*)d_in[5],(const float*)d_in[8]};
  const float* Bv[3] = {(const float*)d_in[3],(const float*)d_in[6],(const float*)d_in[9]};
  const float* Wf = (const float*)d_in[10];
  const float* gf = (const float*)d_in[11];
  const float* bf = (const float*)d_in[12];
  float* out = (float*)d_out;

  k_init<<<64,256>>>();
  k_xx0<<<NPTS/4,256>>>(x);
  for (int l=0;l<3;l++){
    int useCat = (l>0);
    int catOff = useCat ? (l-1)*64 : 0;
    int ldf    = useCat ? CATC : CC;
    k_dist <<<dim3(NN/128, NN/128, BB),256>>>(x, useCat, catOff, ldf);
    k_topk <<<NPTS/8,256>>>();
    k_pq   <<<NPTS/64,256>>>(x, useCat, catOff, ldf, W[l]);
    k_gather<<<NPTS/64,256>>>(l);
    k_efinal<<<NPTS/4,256>>>(l, G[l], Bv[l], l*64);
  }
  k_fgemm<<<dim3(NPTS/128, OUTC/128),256>>>(Wf);
  k_fout <<<BB*OUTC/256,256>>>(gf, bf, out);
}

// round 5
// speedup vs baseline: 2.7447x; 1.2099x over previous
#include <cuda_runtime.h>
#include <cstdint>
#include <cstddef>

#define BB 16
#define NN 2048
#define CC 64
#define KK 20
#define OUTC 1024
#define CATC 192
#define NPTS (BB*NN)
#define EPSF 1e-5f

// ---------------- scratch (static __device__, no allocation) ----------------
__device__ float g_D[(size_t)BB*NN*NN];        // 268MB: neg_dist, reused per layer
__device__ int   g_idx[NPTS*KK];
__device__ float g_PQ[(size_t)NPTS*128];       // [P(64) | Q(64)] per point
__device__ float g_hmax[(size_t)NPTS*CC];
__device__ float g_hmin[(size_t)NPTS*CC];
__device__ float g_cat[(size_t)NPTS*CATC];     // f1|f2|f3
__device__ float g_xx[NPTS];
__device__ float g_s1[3][CC];
__device__ float g_s2[3][CC];
__device__ float g_s1f[OUTC];
__device__ float g_s2f[OUTC];
__device__ unsigned g_fmaxe[BB*OUTC];
__device__ unsigned g_fmine[BB*OUTC];

__device__ __forceinline__ float neg_inf(){ return __int_as_float(0xff800000); }
__device__ __forceinline__ unsigned encf(float f){
  unsigned u = __float_as_uint(f);
  return (u & 0x80000000u) ? ~u : (u | 0x80000000u);
}
__device__ __forceinline__ float decf(unsigned u){
  return __uint_as_float((u & 0x80000000u) ? (u ^ 0x80000000u) : ~u);
}

// ---------------- init ----------------
__global__ void k_init(){
  int i = blockIdx.x*256 + threadIdx.x;
  if (i < BB*OUTC){ g_fmaxe[i]=0u; g_fmine[i]=0xFFFFFFFFu; }
  if (i < OUTC){ g_s1f[i]=0.f; g_s2f[i]=0.f; }
  if (i < 3*CC){ (&g_s1[0][0])[i]=0.f; (&g_s2[0][0])[i]=0.f; }
}

// ---------------- squared norms of input x ---------------------------------
__global__ void k_xx0(const float* __restrict__ x){
  int sub = threadIdx.x >> 6;
  int o   = threadIdx.x & 63;
  int p   = blockIdx.x*4 + sub;
  float v = x[(size_t)p*64 + o];
  float s = v*v;
  #pragma unroll
  for (int off=16; off; off>>=1) s += __shfl_down_sync(0xffffffffu, s, off);
  __shared__ float sm[8];
  if ((threadIdx.x & 31)==0) sm[threadIdx.x>>5] = s;
  __syncthreads();
  if (o==0) g_xx[p] = sm[sub*2] + sm[sub*2+1];
}

// ------- symmetric neg_dist GEMM: only cb>=rb tiles; write tile + mirror ----
__global__ void __launch_bounds__(256) k_dist(const float* __restrict__ xext,
                                              int useCat, int catOff, int ldf){
  if (blockIdx.x < blockIdx.y) return;            // lower triangle: skip
  __shared__ float As[32][136];   // [k][m]
  __shared__ float Bs[32][136];   // [k][n]
  const float* feat = useCat ? (g_cat + catOff) : xext;
  int b = blockIdx.z;
  int rb = blockIdx.y*128, cb = blockIdx.x*128;
  const float* Fb = feat + (size_t)b*NN*ldf;
  int t = threadIdx.x;
  int ty = t>>4, tx = t&15;
  int m0 = ty*8, n0 = tx*8;
  float acc[8][8] = {};
  for (int kc=0; kc<2; kc++){
    __syncthreads();
    #pragma unroll
    for (int i=0;i<4;i++){
      int j = t + i*256;
      int m = j>>3, k4 = (j&7)*4;
      float4 a = *(const float4*)(Fb + (size_t)(rb+m)*ldf + kc*32 + k4);
      As[k4+0][m]=a.x; As[k4+1][m]=a.y; As[k4+2][m]=a.z; As[k4+3][m]=a.w;
      float4 c = *(const float4*)(Fb + (size_t)(cb+m)*ldf + kc*32 + k4);
      Bs[k4+0][m]=c.x; Bs[k4+1][m]=c.y; Bs[k4+2][m]=c.z; Bs[k4+3][m]=c.w;
    }
    __syncthreads();
    #pragma unroll 8
    for (int k=0;k<32;k++){
      float av[8], bv[8];
      *(float4*)&av[0] = *(const float4*)&As[k][m0];
      *(float4*)&av[4] = *(const float4*)&As[k][m0+4];
      *(float4*)&bv[0] = *(const float4*)&Bs[k][n0];
      *(float4*)&bv[4] = *(const float4*)&Bs[k][n0+4];
      #pragma unroll
      for (int i=0;i<8;i++)
        #pragma unroll
        for (int j2=0;j2<8;j2++)
          acc[i][j2] += av[i]*bv[j2];
    }
  }
  int grow = b*NN + rb + m0;
  int gcol = b*NN + cb + n0;
  float xr[8], xc[8];
  #pragma unroll
  for (int i=0;i<8;i++)  xr[i]=g_xx[grow+i];
  #pragma unroll
  for (int j2=0;j2<8;j2++) xc[j2]=g_xx[gcol+j2];
  float d[8][8];
  #pragma unroll
  for (int i=0;i<8;i++)
    #pragma unroll
    for (int j2=0;j2<8;j2++)
      d[i][j2] = 2.f*acc[i][j2]-xr[i]-xc[j2];
  #pragma unroll
  for (int i=0;i<8;i++){
    float* dst = &g_D[(size_t)(grow+i)*NN + cb + n0];
    *(float4*)dst     = *(float4*)&d[i][0];
    *(float4*)(dst+4) = *(float4*)&d[i][4];
  }
  if (cb > rb){
    // mirror: D[cb+j][rb+i] = d[i][j], contiguous along i -> float4 stores
    #pragma unroll
    for (int j2=0;j2<8;j2++){
      float4 w1, w2;
      w1.x=d[0][j2]; w1.y=d[1][j2]; w1.z=d[2][j2]; w1.w=d[3][j2];
      w2.x=d[4][j2]; w2.y=d[5][j2]; w2.z=d[6][j2]; w2.w=d[7][j2];
      float* dst = &g_D[(size_t)(gcol+j2)*NN + rb + m0];
      *(float4*)dst     = w1;
      *(float4*)(dst+4) = w2;
    }
  }
}

// ------- top-20 per row: float4 scan + packed u64 warp insertion ------------
__global__ void __launch_bounds__(256) k_topk(){
  int w = threadIdx.x>>5, lane = threadIdx.x&31;
  int row = blockIdx.x*8 + w;
  const float4* drow4 = (const float4*)(g_D + (size_t)row*NN);

  unsigned long long rk = 0ull;   // running top-32, sorted desc (lane0 best)
  unsigned long long thr = 0ull;  // key at rank 19 (20th best)

  for (int b=0; b<16; b++){
    int e = b*32 + lane;
    float4 dv = __ldg(&drow4[e]);
    int i0 = e*4;
    unsigned long long k0 = ((unsigned long long)encf(dv.x) << 32) | (unsigned)(~(i0+0));
    unsigned long long k1 = ((unsigned long long)encf(dv.y) << 32) | (unsigned)(~(i0+1));
    unsigned long long k2 = ((unsigned long long)encf(dv.z) << 32) | (unsigned)(~(i0+2));
    unsigned long long k3 = ((unsigned long long)encf(dv.w) << 32) | (unsigned)(~(i0+3));
    unsigned long long best = k0 > k1 ? k0 : k1;
    unsigned long long b23  = k2 > k3 ? k2 : k3;
    if (b23 > best) best = b23;
    if (!__ballot_sync(0xffffffffu, best > thr)) continue;

    unsigned long long keys[4] = {k0,k1,k2,k3};
    #pragma unroll
    for (int q=0;q<4;q++){
      unsigned long long key = keys[q];
      unsigned m = __ballot_sync(0xffffffffu, key > thr);
      while (m){
        int src = __ffs(m) - 1;
        unsigned long long ck = __shfl_sync(0xffffffffu, key, src);
        unsigned bet = __ballot_sync(0xffffffffu, rk > ck);
        int pos = __popc(bet);
        unsigned long long prev = __shfl_up_sync(0xffffffffu, rk, 1);
        if (lane == pos)      rk = ck;
        else if (lane > pos)  rk = prev;
        thr = __shfl_sync(0xffffffffu, rk, 19);
        if (lane == src) key = 0ull;
        m = __ballot_sync(0xffffffffu, key > thr);
      }
    }
  }
  if (lane < KK) g_idx[row*KK + lane] = (int)(~(unsigned)(rk & 0xffffffffu));
}

// ---------------- P/Q projection -------------------------------------------
__global__ void __launch_bounds__(256) k_pq(const float* __restrict__ xext,
                                            int useCat, int catOff, int ldf,
                                            const float* __restrict__ W){
  const float* feat = useCat ? (g_cat + catOff) : xext;
  __shared__ float Fs[64][64];    // [m][k]
  __shared__ float Ws[64][128];   // [k][j]
  int t = threadIdx.x;
  int mb = blockIdx.x*64;
  #pragma unroll
  for (int i=0;i<4;i++){
    int j = t + i*256;
    int m = j>>4, k4=(j&15)*4;
    float4 a = *(const float4*)(feat + (size_t)(mb+m)*ldf + k4);
    *(float4*)&Fs[m][k4] = a;
  }
  #pragma unroll
  for (int i=0;i<32;i++){
    int l = t + i*256;
    int k = l>>7, j = l&127;
    Ws[k][j] = (j<64)? W[j*128 + k] : W[(j-64)*128 + 64 + k];
  }
  __syncthreads();
  int ty=t>>4, tx=t&15;
  int m0=ty*4, o0=tx*8;
  float acc[4][8] = {};
  #pragma unroll 8
  for (int k=0;k<64;k++){
    float av[4];
    #pragma unroll
    for (int i=0;i<4;i++) av[i]=Fs[m0+i][k];
    float4 w0=*(const float4*)&Ws[k][o0];
    float4 w1=*(const float4*)&Ws[k][o0+4];
    float wv[8]={w0.x,w0.y,w0.z,w0.w,w1.x,w1.y,w1.z,w1.w};
    #pragma unroll
    for (int i=0;i<4;i++)
      #pragma unroll
      for (int j2=0;j2<8;j2++)
        acc[i][j2] += av[i]*wv[j2];
  }
  #pragma unroll
  for (int i=0;i<4;i++){
    float* dst = g_PQ + (size_t)(mb+m0+i)*128 + o0;
    float4 u,vv;
    u.x=acc[i][0]; u.y=acc[i][1]; u.z=acc[i][2]; u.w=acc[i][3];
    vv.x=acc[i][4]; vv.y=acc[i][5]; vv.z=acc[i][6]; vv.w=acc[i][7];
    *(float4*)dst = u;
    *(float4*)(dst+4) = vv;
  }
}

// -------- gather: h = P[m] + (Q[n]-P[n]); max/min over k + channel stats ----
__global__ void __launch_bounds__(256) k_gather(int layer){
  __shared__ float ss1[64], ss2[64];
  int t = threadIdx.x;
  if (t<64){ ss1[t]=0.f; ss2[t]=0.f; }
  __syncthreads();
  int w=t>>5, lane=t&31;
  float ls1a=0.f, ls1b=0.f, ls2a=0.f, ls2b=0.f;
  for (int p=0;p<8;p++){
    int point = blockIdx.x*64 + w*8 + p;
    int b = point >> 11;
    const float* pqn = g_PQ + (size_t)point*128;
    float ra  = pqn[64+lane] - pqn[lane];
    float rb2 = pqn[96+lane] - pqn[32+lane];
    float hxa=neg_inf(), hxb=neg_inf();
    float hna=-neg_inf(), hnb=-neg_inf();
    const int* ids = g_idx + point*KK;
    #pragma unroll 4
    for (int k=0;k<KK;k++){
      int m = ids[k];
      const float* pm = g_PQ + (size_t)((b<<11)+m)*128;
      float ha = pm[lane]    + ra;
      float hb = pm[32+lane] + rb2;
      ls1a+=ha; ls2a+=ha*ha; hxa=fmaxf(hxa,ha); hna=fminf(hna,ha);
      ls1b+=hb; ls2b+=hb*hb; hxb=fmaxf(hxb,hb); hnb=fminf(hnb,hb);
    }
    g_hmax[(size_t)point*64+lane]=hxa; g_hmax[(size_t)point*64+32+lane]=hxb;
    g_hmin[(size_t)point*64+lane]=hna; g_hmin[(size_t)point*64+32+lane]=hnb;
  }
  atomicAdd(&ss1[lane],    ls1a); atomicAdd(&ss1[lane+32], ls1b);
  atomicAdd(&ss2[lane],    ls2a); atomicAdd(&ss2[lane+32], ls2b);
  __syncthreads();
  if (t<64){ atomicAdd(&g_s1[layer][t], ss1[t]); atomicAdd(&g_s2[layer][t], ss2[t]); }
}

// -------- finalize edge layer: BN+lrelu (max-over-k done) -> cat, xx --------
__global__ void k_efinal(int layer, const float* __restrict__ gg,
                         const float* __restrict__ bbv, int catOff){
  int sub = threadIdx.x>>6;
  int o   = threadIdx.x & 63;
  int p   = blockIdx.x*4 + sub;
  const float cnt = (float)NPTS * (float)KK;
  float mean = g_s1[layer][o]/cnt;
  float var  = g_s2[layer][o]/cnt - mean*mean;
  float scale = rsqrtf(var + EPSF) * gg[o];
  float shift = bbv[o] - mean*scale;
  float h = (scale>=0.f)? g_hmax[(size_t)p*64+o] : g_hmin[(size_t)p*64+o];
  float y = h*scale + shift;
  y = (y>=0.f)? y : 0.2f*y;
  g_cat[(size_t)p*CATC + catOff + o] = y;
  float s = y*y;
  #pragma unroll
  for (int off=16; off; off>>=1) s += __shfl_down_sync(0xffffffffu, s, off);
  __shared__ float sm[8];
  if ((threadIdx.x&31)==0) sm[threadIdx.x>>5]=s;
  __syncthreads();
  if (o==0) g_xx[p] = sm[sub*2]+sm[sub*2+1];
}

// -------- final GEMM: 128x128 tile, 8x8/thread, k chunked by 32 -------------
__global__ void __launch_bounds__(256) k_fgemm(const float* __restrict__ Wf){
  __shared__ float Fs[32][136];   // [k][m]
  __shared__ float Ws[32][136];   // [k][j]
  int t = threadIdx.x;
  int rb = blockIdx.x*128;
  int ob = blockIdx.y*128;
  int b  = rb >> 11;
  int ty=t>>4, tx=t&15;
  int m0=ty*8, o0=tx*8;
  float acc[8][8] = {};
  for (int kc=0;kc<6;kc++){
    __syncthreads();
    #pragma unroll
    for (int i=0;i<4;i++){
      int j = t + i*256;
      int m = j>>3, k4=(j&7)*4;
      float4 a = *(const float4*)(g_cat + (size_t)(rb+m)*CATC + kc*32 + k4);
      Fs[k4+0][m]=a.x; Fs[k4+1][m]=a.y; Fs[k4+2][m]=a.z; Fs[k4+3][m]=a.w;
    }
    #pragma unroll
    for (int i=0;i<16;i++){
      int l = t + i*256;
      int k = l>>7, j = l&127;
      Ws[k][j] = Wf[(size_t)(ob+j)*CATC + kc*32 + k];
    }
    __syncthreads();
    #pragma unroll 8
    for (int k=0;k<32;k++){
      float av[8], wv[8];
      *(float4*)&av[0] = *(const float4*)&Fs[k][m0];
      *(float4*)&av[4] = *(const float4*)&Fs[k][m0+4];
      *(float4*)&wv[0] = *(const float4*)&Ws[k][o0];
      *(float4*)&wv[4] = *(const float4*)&Ws[k][o0+4];
      #pragma unroll
      for (int i=0;i<8;i++)
        #pragma unroll
        for (int j2=0;j2<8;j2++)
          acc[i][j2] += av[i]*wv[j2];
    }
  }
  __syncthreads();
  float* red1 = &Fs[0][0];          // 16x128
  float* red2 = &Ws[0][0];          // 16x128
  #pragma unroll
  for (int j2=0;j2<8;j2++){
    float mx = acc[0][j2], mn = acc[0][j2];
    #pragma unroll
    for (int i=1;i<8;i++){ mx = fmaxf(mx, acc[i][j2]); mn = fminf(mn, acc[i][j2]); }
    red1[ty*128 + o0 + j2] = mx;
    red2[ty*128 + o0 + j2] = mn;
  }
  __syncthreads();
  if (t < 128){
    float mx = neg_inf(), mn = -neg_inf();
    #pragma unroll
    for (int r=0;r<16;r++){
      mx = fmaxf(mx, red1[r*128+t]);
      mn = fminf(mn, red2[r*128+t]);
    }
    atomicMax(&g_fmaxe[b*OUTC + ob + t], encf(mx));
    atomicMin(&g_fmine[b*OUTC + ob + t], encf(mn));
  }
  __syncthreads();
  #pragma unroll
  for (int j2=0;j2<8;j2++){
    float s = 0.f, q = 0.f;
    #pragma unroll
    for (int i=0;i<8;i++){ s += acc[i][j2]; q += acc[i][j2]*acc[i][j2]; }
    red1[ty*128 + o0 + j2] = s;
    red2[ty*128 + o0 + j2] = q;
  }
  __syncthreads();
  if (t < 128){
    float s=0.f, q=0.f;
    #pragma unroll
    for (int r=0;r<16;r++){ s += red1[r*128+t]; q += red2[r*128+t]; }
    atomicAdd(&g_s1f[ob + t], s);
    atomicAdd(&g_s2f[ob + t], q);
  }
}

// -------- final BN + lrelu + pick max/min ----------------------------------
__global__ void k_fout(const float* __restrict__ gf, const float* __restrict__ bf,
                       float* __restrict__ out){
  int i = blockIdx.x*256 + threadIdx.x;   // 0..16383
  int o = i & (OUTC-1);
  const float cnt = (float)NPTS;
  float mean = g_s1f[o]/cnt;
  float var  = g_s2f[o]/cnt - mean*mean;
  float scale = rsqrtf(var + EPSF) * gf[o];
  float shift = bf[o] - mean*scale;
  float h = (scale>=0.f)? decf(g_fmaxe[i]) : decf(g_fmine[i]);
  float y = h*scale + shift;
  out[i] = (y>=0.f)? y : 0.2f*y;
}

extern "C" void kernel_launch(void* const* d_in, const int* in_sizes, int n_in,
                              void* d_out, int out_size){
  const float* x   = (const float*)d_in[0];
  const float* W[3]  = {(const float*)d_in[1],(const float*)d_in[4],(const float*)d_in[7]};
  const float* G[3]  = {(const float*)d_in[2],(const float*)d_in[5],(const float*)d_in[8]};
  const float* Bv[3] = {(const float*)d_in[3],(const float*)d_in[6],(const float*)d_in[9]};
  const float* Wf = (const float*)d_in[10];
  const float* gf = (const float*)d_in[11];
  const float* bf = (const float*)d_in[12];
  float* out = (float*)d_out;

  k_init<<<64,256>>>();
  k_xx0<<<NPTS/4,256>>>(x);
  for (int l=0;l<3;l++){
    int useCat = (l>0);
    int catOff = useCat ? (l-1)*64 : 0;
    int ldf    = useCat ? CATC : CC;
    k_dist <<<dim3(NN/128, NN/128, BB),256>>>(x, useCat, catOff, ldf);
    k_topk <<<NPTS/8,256>>>();
    k_pq   <<<NPTS/64,256>>>(x, useCat, catOff, ldf, W[l]);
    k_gather<<<NPTS/64,256>>>(l);
    k_efinal<<<NPTS/4,256>>>(l, G[l], Bv[l], l*64);
  }
  k_fgemm<<<dim3(NPTS/128, OUTC/128),256>>>(Wf);
  k_fout <<<BB*OUTC/256,256>>>(gf, bf, out);
}

// round 6
// speedup vs baseline: 3.2018x; 1.1666x over previous
#include <cuda_runtime.h>
#include <cuda_bf16.h>
#include <cstdint>
#include <cstddef>

#define BB 16
#define NN 2048
#define CC 64
#define KK 20
#define OUTC 1024
#define CATC 192
#define NPTS (BB*NN)
#define EPSF 1e-5f

// ---------------- scratch (static __device__, no allocation) ----------------
__device__ float g_D[(size_t)BB*NN*NN];        // 268MB: neg_dist, reused per layer
__device__ int   g_idx[NPTS*KK];
__device__ float g_PQ[(size_t)NPTS*128];       // [P(64) | Q(64)] per point
__device__ float g_hmax[(size_t)NPTS*CC];
__device__ float g_hmin[(size_t)NPTS*CC];
__device__ float g_cat[(size_t)NPTS*CATC];     // f1|f2|f3
__device__ float g_xx[NPTS];
__device__ float g_s1[3][CC];
__device__ float g_s2[3][CC];
__device__ float g_s1f[OUTC];
__device__ float g_s2f[OUTC];
__device__ unsigned g_fmaxe[BB*OUTC];
__device__ unsigned g_fmine[BB*OUTC];
__device__ __nv_bfloat16 g_A2[(size_t)NPTS*576];   // [catH | catH | catL]
__device__ __nv_bfloat16 g_B2[(size_t)OUTC*576];   // [WfH  | WfL  | WfH ]

__device__ __forceinline__ float neg_inf(){ return __int_as_float(0xff800000); }
__device__ __forceinline__ unsigned encf(float f){
  unsigned u = __float_as_uint(f);
  return (u & 0x80000000u) ? ~u : (u | 0x80000000u);
}
__device__ __forceinline__ float decf(unsigned u){
  return __uint_as_float((u & 0x80000000u) ? (u ^ 0x80000000u) : ~u);
}
__device__ __forceinline__ unsigned smem_u32(const void* p){
  return (unsigned)__cvta_generic_to_shared(p);
}

// ---------------- init ----------------
__global__ void k_init(){
  int i = blockIdx.x*256 + threadIdx.x;
  if (i < BB*OUTC){ g_fmaxe[i]=0u; g_fmine[i]=0xFFFFFFFFu; }
  if (i < OUTC){ g_s1f[i]=0.f; g_s2f[i]=0.f; }
  if (i < 3*CC){ (&g_s1[0][0])[i]=0.f; (&g_s2[0][0])[i]=0.f; }
}

// ---------------- squared norms of input x ---------------------------------
__global__ void k_xx0(const float* __restrict__ x){
  int sub = threadIdx.x >> 6;
  int o   = threadIdx.x & 63;
  int p   = blockIdx.x*4 + sub;
  float v = x[(size_t)p*64 + o];
  float s = v*v;
  #pragma unroll
  for (int off=16; off; off>>=1) s += __shfl_down_sync(0xffffffffu, s, off);
  __shared__ float sm[8];
  if ((threadIdx.x & 31)==0) sm[threadIdx.x>>5] = s;
  __syncthreads();
  if (o==0) g_xx[p] = sm[sub*2] + sm[sub*2+1];
}

// ------- symmetric neg_dist GEMM: only cb>=rb tiles; write tile + mirror ----
__global__ void __launch_bounds__(256) k_dist(const float* __restrict__ xext,
                                              int useCat, int catOff, int ldf){
  if (blockIdx.x < blockIdx.y) return;            // lower triangle: skip
  __shared__ float As[32][136];   // [k][m]
  __shared__ float Bs[32][136];   // [k][n]
  const float* feat = useCat ? (g_cat + catOff) : xext;
  int b = blockIdx.z;
  int rb = blockIdx.y*128, cb = blockIdx.x*128;
  const float* Fb = feat + (size_t)b*NN*ldf;
  int t = threadIdx.x;
  int ty = t>>4, tx = t&15;
  int m0 = ty*8, n0 = tx*8;
  float acc[8][8] = {};
  for (int kc=0; kc<2; kc++){
    __syncthreads();
    #pragma unroll
    for (int i=0;i<4;i++){
      int j = t + i*256;
      int m = j>>3, k4 = (j&7)*4;
      float4 a = *(const float4*)(Fb + (size_t)(rb+m)*ldf + kc*32 + k4);
      As[k4+0][m]=a.x; As[k4+1][m]=a.y; As[k4+2][m]=a.z; As[k4+3][m]=a.w;
      float4 c = *(const float4*)(Fb + (size_t)(cb+m)*ldf + kc*32 + k4);
      Bs[k4+0][m]=c.x; Bs[k4+1][m]=c.y; Bs[k4+2][m]=c.z; Bs[k4+3][m]=c.w;
    }
    __syncthreads();
    #pragma unroll 8
    for (int k=0;k<32;k++){
      float av[8], bv[8];
      *(float4*)&av[0] = *(const float4*)&As[k][m0];
      *(float4*)&av[4] = *(const float4*)&As[k][m0+4];
      *(float4*)&bv[0] = *(const float4*)&Bs[k][n0];
      *(float4*)&bv[4] = *(const float4*)&Bs[k][n0+4];
      #pragma unroll
      for (int i=0;i<8;i++)
        #pragma unroll
        for (int j2=0;j2<8;j2++)
          acc[i][j2] += av[i]*bv[j2];
    }
  }
  int grow = b*NN + rb + m0;
  int gcol = b*NN + cb + n0;
  float xr[8], xc[8];
  #pragma unroll
  for (int i=0;i<8;i++)  xr[i]=g_xx[grow+i];
  #pragma unroll
  for (int j2=0;j2<8;j2++) xc[j2]=g_xx[gcol+j2];
  float d[8][8];
  #pragma unroll
  for (int i=0;i<8;i++)
    #pragma unroll
    for (int j2=0;j2<8;j2++)
      d[i][j2] = 2.f*acc[i][j2]-xr[i]-xc[j2];
  #pragma unroll
  for (int i=0;i<8;i++){
    float* dst = &g_D[(size_t)(grow+i)*NN + cb + n0];
    *(float4*)dst     = *(float4*)&d[i][0];
    *(float4*)(dst+4) = *(float4*)&d[i][4];
  }
  if (cb > rb){
    #pragma unroll
    for (int j2=0;j2<8;j2++){
      float4 w1, w2;
      w1.x=d[0][j2]; w1.y=d[1][j2]; w1.z=d[2][j2]; w1.w=d[3][j2];
      w2.x=d[4][j2]; w2.y=d[5][j2]; w2.z=d[6][j2]; w2.w=d[7][j2];
      float* dst = &g_D[(size_t)(gcol+j2)*NN + rb + m0];
      *(float4*)dst     = w1;
      *(float4*)(dst+4) = w2;
    }
  }
}

// ------- top-20 per row: float-pruned scan + packed u64 warp insertion ------
__global__ void __launch_bounds__(256) k_topk(){
  int w = threadIdx.x>>5, lane = threadIdx.x&31;
  int row = blockIdx.x*8 + w;
  const float4* drow4 = (const float4*)(g_D + (size_t)row*NN);

  // init with key(-inf, idx=INT_MAX): real keys always larger
  unsigned long long rk  = 0x007fffff80000000ull;
  unsigned long long thr = 0x007fffff80000000ull;
  float vthr = neg_inf();

  for (int b=0; b<16; b++){
    int e = b*32 + lane;
    float4 dv = __ldg(&drow4[e]);
    float bmax = fmaxf(fmaxf(dv.x, dv.y), fmaxf(dv.z, dv.w));
    if (!__ballot_sync(0xffffffffu, bmax >= vthr)) continue;

    int i0 = e*4;
    unsigned long long keys[4];
    keys[0] = ((unsigned long long)encf(dv.x) << 32) | (unsigned)(~(i0+0));
    keys[1] = ((unsigned long long)encf(dv.y) << 32) | (unsigned)(~(i0+1));
    keys[2] = ((unsigned long long)encf(dv.z) << 32) | (unsigned)(~(i0+2));
    keys[3] = ((unsigned long long)encf(dv.w) << 32) | (unsigned)(~(i0+3));
    #pragma unroll
    for (int q=0;q<4;q++){
      unsigned long long key = keys[q];
      unsigned m = __ballot_sync(0xffffffffu, key > thr);
      while (m){
        int src = __ffs(m) - 1;
        unsigned long long ck = __shfl_sync(0xffffffffu, key, src);
        unsigned bet = __ballot_sync(0xffffffffu, rk > ck);
        int pos = __popc(bet);
        unsigned long long prev = __shfl_up_sync(0xffffffffu, rk, 1);
        if (lane == pos)      rk = ck;
        else if (lane > pos)  rk = prev;
        thr = __shfl_sync(0xffffffffu, rk, 19);
        if (lane == src) key = 0ull;
        m = __ballot_sync(0xffffffffu, key > thr);
      }
    }
    vthr = decf((unsigned)(thr >> 32));
  }
  if (lane < KK) g_idx[row*KK + lane] = (int)(~(unsigned)(rk & 0xffffffffu));
}

// ---------------- P/Q projection -------------------------------------------
__global__ void __launch_bounds__(256) k_pq(const float* __restrict__ xext,
                                            int useCat, int catOff, int ldf,
                                            const float* __restrict__ W){
  const float* feat = useCat ? (g_cat + catOff) : xext;
  __shared__ float Fs[64][64];    // [m][k]
  __shared__ float Ws[64][128];   // [k][j]
  int t = threadIdx.x;
  int mb = blockIdx.x*64;
  #pragma unroll
  for (int i=0;i<4;i++){
    int j = t + i*256;
    int m = j>>4, k4=(j&15)*4;
    float4 a = *(const float4*)(feat + (size_t)(mb+m)*ldf + k4);
    *(float4*)&Fs[m][k4] = a;
  }
  #pragma unroll
  for (int i=0;i<32;i++){
    int l = t + i*256;
    int k = l>>7, j = l&127;
    Ws[k][j] = (j<64)? W[j*128 + k] : W[(j-64)*128 + 64 + k];
  }
  __syncthreads();
  int ty=t>>4, tx=t&15;
  int m0=ty*4, o0=tx*8;
  float acc[4][8] = {};
  #pragma unroll 8
  for (int k=0;k<64;k++){
    float av[4];
    #pragma unroll
    for (int i=0;i<4;i++) av[i]=Fs[m0+i][k];
    float4 w0=*(const float4*)&Ws[k][o0];
    float4 w1=*(const float4*)&Ws[k][o0+4];
    float wv[8]={w0.x,w0.y,w0.z,w0.w,w1.x,w1.y,w1.z,w1.w};
    #pragma unroll
    for (int i=0;i<4;i++)
      #pragma unroll
      for (int j2=0;j2<8;j2++)
        acc[i][j2] += av[i]*wv[j2];
  }
  #pragma unroll
  for (int i=0;i<4;i++){
    float* dst = g_PQ + (size_t)(mb+m0+i)*128 + o0;
    float4 u,vv;
    u.x=acc[i][0]; u.y=acc[i][1]; u.z=acc[i][2]; u.w=acc[i][3];
    vv.x=acc[i][4]; vv.y=acc[i][5]; vv.z=acc[i][6]; vv.w=acc[i][7];
    *(float4*)dst = u;
    *(float4*)(dst+4) = vv;
  }
}

// -------- gather: h = P[m] + (Q[n]-P[n]); max/min over k + channel stats ----
__global__ void __launch_bounds__(256) k_gather(int layer){
  __shared__ float ss1[64], ss2[64];
  int t = threadIdx.x;
  if (t<64){ ss1[t]=0.f; ss2[t]=0.f; }
  __syncthreads();
  int w=t>>5, lane=t&31;
  float ls1a=0.f, ls1b=0.f, ls2a=0.f, ls2b=0.f;
  for (int p=0;p<8;p++){
    int point = blockIdx.x*64 + w*8 + p;
    int b = point >> 11;
    const float* pqn = g_PQ + (size_t)point*128;
    float ra  = pqn[64+lane] - pqn[lane];
    float rb2 = pqn[96+lane] - pqn[32+lane];
    float hxa=neg_inf(), hxb=neg_inf();
    float hna=-neg_inf(), hnb=-neg_inf();
    const int* ids = g_idx + point*KK;
    #pragma unroll 4
    for (int k=0;k<KK;k++){
      int m = ids[k];
      const float* pm = g_PQ + (size_t)((b<<11)+m)*128;
      float ha = pm[lane]    + ra;
      float hb = pm[32+lane] + rb2;
      ls1a+=ha; ls2a+=ha*ha; hxa=fmaxf(hxa,ha); hna=fminf(hna,ha);
      ls1b+=hb; ls2b+=hb*hb; hxb=fmaxf(hxb,hb); hnb=fminf(hnb,hb);
    }
    g_hmax[(size_t)point*64+lane]=hxa; g_hmax[(size_t)point*64+32+lane]=hxb;
    g_hmin[(size_t)point*64+lane]=hna; g_hmin[(size_t)point*64+32+lane]=hnb;
  }
  atomicAdd(&ss1[lane],    ls1a); atomicAdd(&ss1[lane+32], ls1b);
  atomicAdd(&ss2[lane],    ls2a); atomicAdd(&ss2[lane+32], ls2b);
  __syncthreads();
  if (t<64){ atomicAdd(&g_s1[layer][t], ss1[t]); atomicAdd(&g_s2[layer][t], ss2[t]); }
}

// -------- finalize edge layer: BN+lrelu (max-over-k done) -> cat, xx --------
__global__ void k_efinal(int layer, const float* __restrict__ gg,
                         const float* __restrict__ bbv, int catOff){
  int sub = threadIdx.x>>6;
  int o   = threadIdx.x & 63;
  int p   = blockIdx.x*4 + sub;
  const float cnt = (float)NPTS * (float)KK;
  float mean = g_s1[layer][o]/cnt;
  float var  = g_s2[layer][o]/cnt - mean*mean;
  float scale = rsqrtf(var + EPSF) * gg[o];
  float shift = bbv[o] - mean*scale;
  float h = (scale>=0.f)? g_hmax[(size_t)p*64+o] : g_hmin[(size_t)p*64+o];
  float y = h*scale + shift;
  y = (y>=0.f)? y : 0.2f*y;
  g_cat[(size_t)p*CATC + catOff + o] = y;
  float s = y*y;
  #pragma unroll
  for (int off=16; off; off>>=1) s += __shfl_down_sync(0xffffffffu, s, off);
  __shared__ float sm[8];
  if ((threadIdx.x&31)==0) sm[threadIdx.x>>5]=s;
  __syncthreads();
  if (o==0) g_xx[p] = sm[sub*2]+sm[sub*2+1];
}

// -------- bf16 split conversions for final GEMM -----------------------------
__global__ void k_cvtA(){
  int idx = blockIdx.x*256 + threadIdx.x;      // NPTS*CATC
  int p = idx / CATC, c = idx - p*CATC;
  float x = g_cat[(size_t)p*CATC + c];
  __nv_bfloat16 h = __float2bfloat16(x);
  __nv_bfloat16 lo = __float2bfloat16(x - __bfloat162float(h));
  size_t base = (size_t)p*576;
  g_A2[base + c]       = h;
  g_A2[base + 192 + c] = h;
  g_A2[base + 384 + c] = lo;
}
__global__ void k_cvtB(const float* __restrict__ Wf){
  int idx = blockIdx.x*256 + threadIdx.x;      // OUTC*CATC
  int o = idx / CATC, c = idx - o*CATC;
  float x = Wf[(size_t)o*CATC + c];
  __nv_bfloat16 h = __float2bfloat16(x);
  __nv_bfloat16 lo = __float2bfloat16(x - __bfloat162float(h));
  size_t base = (size_t)o*576;
  g_B2[base + c]       = h;
  g_B2[base + 192 + c] = lo;
  g_B2[base + 384 + c] = h;
}

// -------- final GEMM via mma.sync bf16 (K=576 split), fused stats epilogue --
__global__ void __launch_bounds__(256) k_fgemm(){
  __shared__ __nv_bfloat16 sA[128][40];
  __shared__ __nv_bfloat16 sB[128][40];
  __shared__ float rmx[2][128], rmn[2][128], rs[2][128], rq[2][128];
  int t = threadIdx.x, lane = t&31, wid = t>>5;
  int wm = wid>>2, wn = wid&3;
  int rb = blockIdx.x*128, ob = blockIdx.y*128;
  int b = rb>>11;
  float acc[4][4][4];
  #pragma unroll
  for (int i=0;i<4;i++)
    #pragma unroll
    for (int j=0;j<4;j++)
      #pragma unroll
      for (int e=0;e<4;e++) acc[i][j][e]=0.f;

  for (int kc=0; kc<18; kc++){
    __syncthreads();
    #pragma unroll
    for (int i=0;i<2;i++){
      int s = t*2 + i;                 // 0..511
      int row = s>>2, seg = (s&3)*8;
      *(uint4*)&sA[row][seg] = *(const uint4*)&g_A2[(size_t)(rb+row)*576 + kc*32 + seg];
      *(uint4*)&sB[row][seg] = *(const uint4*)&g_B2[(size_t)(ob+row)*576 + kc*32 + seg];
    }
    __syncthreads();
    #pragma unroll
    for (int ks=0; ks<2; ks++){
      unsigned af[4][4];
      #pragma unroll
      for (int i=0;i<4;i++){
        int row = wm*64 + i*16 + (lane & 15);
        int col = ks*16 + (lane>>4)*8;
        unsigned addr = smem_u32(&sA[row][col]);
        asm volatile("ldmatrix.sync.aligned.m8n8.x4.shared.b16 {%0,%1,%2,%3}, [%4];"
          : "=r"(af[i][0]),"=r"(af[i][1]),"=r"(af[i][2]),"=r"(af[i][3]) : "r"(addr));
      }
      unsigned bfm[4][2];
      #pragma unroll
      for (int j=0;j<4;j++){
        int l16 = lane & 15;
        int row = wn*32 + j*8 + (l16 & 7);
        int col = ks*16 + (l16>>3)*8;
        unsigned addr = smem_u32(&sB[row][col]);
        asm volatile("ldmatrix.sync.aligned.m8n8.x2.shared.b16 {%0,%1}, [%2];"
          : "=r"(bfm[j][0]),"=r"(bfm[j][1]) : "r"(addr));
      }
      #pragma unroll
      for (int i=0;i<4;i++)
        #pragma unroll
        for (int j=0;j<4;j++){
          asm volatile(
            "mma.sync.aligned.m16n8k16.row.col.f32.bf16.bf16.f32 "
            "{%0,%1,%2,%3}, {%4,%5,%6,%7}, {%8,%9}, {%0,%1,%2,%3};"
            : "+f"(acc[i][j][0]),"+f"(acc[i][j][1]),"+f"(acc[i][j][2]),"+f"(acc[i][j][3])
            : "r"(af[i][0]),"r"(af[i][1]),"r"(af[i][2]),"r"(af[i][3]),
              "r"(bfm[j][0]),"r"(bfm[j][1]));
        }
    }
  }
  // ---- fused stats epilogue ----
  #pragma unroll
  for (int j=0;j<4;j++){
    #pragma unroll
    for (int e=0;e<2;e++){
      float v0 = acc[0][j][e], v1 = acc[0][j][e+2];
      float mx = fmaxf(v0,v1), mn = fminf(v0,v1);
      float s = v0+v1, q = v0*v0+v1*v1;
      #pragma unroll
      for (int i=1;i<4;i++){
        v0 = acc[i][j][e]; v1 = acc[i][j][e+2];
        mx = fmaxf(mx, fmaxf(v0,v1));
        mn = fminf(mn, fminf(v0,v1));
        s += v0+v1; q += v0*v0+v1*v1;
      }
      #pragma unroll
      for (int off=4; off<32; off<<=1){
        mx = fmaxf(mx, __shfl_xor_sync(0xffffffffu, mx, off));
        mn = fminf(mn, __shfl_xor_sync(0xffffffffu, mn, off));
        s += __shfl_xor_sync(0xffffffffu, s, off);
        q += __shfl_xor_sync(0xffffffffu, q, off);
      }
      if (lane < 4){
        int col = wn*32 + j*8 + lane*2 + e;
        rmx[wm][col]=mx; rmn[wm][col]=mn; rs[wm][col]=s; rq[wm][col]=q;
      }
    }
  }
  __syncthreads();
  if (t < 128){
    float mx = fmaxf(rmx[0][t], rmx[1][t]);
    float mn = fminf(rmn[0][t], rmn[1][t]);
    float s  = rs[0][t] + rs[1][t];
    float q  = rq[0][t] + rq[1][t];
    atomicMax(&g_fmaxe[b*OUTC + ob + t], encf(mx));
    atomicMin(&g_fmine[b*OUTC + ob + t], encf(mn));
    atomicAdd(&g_s1f[ob + t], s);
    atomicAdd(&g_s2f[ob + t], q);
  }
}

// -------- final BN + lrelu + pick max/min ----------------------------------
__global__ void k_fout(const float* __restrict__ gf, const float* __restrict__ bf,
                       float* __restrict__ out){
  int i = blockIdx.x*256 + threadIdx.x;   // 0..16383
  int o = i & (OUTC-1);
  const float cnt = (float)NPTS;
  float mean = g_s1f[o]/cnt;
  float var  = g_s2f[o]/cnt - mean*mean;
  float scale = rsqrtf(var + EPSF) * gf[o];
  float shift = bf[o] - mean*scale;
  float h = (scale>=0.f)? decf(g_fmaxe[i]) : decf(g_fmine[i]);
  float y = h*scale + shift;
  out[i] = (y>=0.f)? y : 0.2f*y;
}

extern "C" void kernel_launch(void* const* d_in, const int* in_sizes, int n_in,
                              void* d_out, int out_size){
  const float* x   = (const float*)d_in[0];
  const float* W[3]  = {(const float*)d_in[1],(const float*)d_in[4],(const float*)d_in[7]};
  const float* G[3]  = {(const float*)d_in[2],(const float*)d_in[5],(const float*)d_in[8]};
  const float* Bv[3] = {(const float*)d_in[3],(const float*)d_in[6],(const float*)d_in[9]};
  const float* Wf = (const float*)d_in[10];
  const float* gf = (const float*)d_in[11];
  const float* bf = (const float*)d_in[12];
  float* out = (float*)d_out;

  k_init<<<64,256>>>();
  k_xx0<<<NPTS/4,256>>>(x);
  for (int l=0;l<3;l++){
    int useCat = (l>0);
    int catOff = useCat ? (l-1)*64 : 0;
    int ldf    = useCat ? CATC : CC;
    k_dist <<<dim3(NN/128, NN/128, BB),256>>>(x, useCat, catOff, ldf);
    k_topk <<<NPTS/8,256>>>();
    k_pq   <<<NPTS/64,256>>>(x, useCat, catOff, ldf, W[l]);
    k_gather<<<NPTS/64,256>>>(l);
    k_efinal<<<NPTS/4,256>>>(l, G[l], Bv[l], l*64);
  }
  k_cvtA<<<(NPTS*CATC)/256,256>>>();
  k_cvtB<<<(OUTC*CATC)/256,256>>>(Wf);
  k_fgemm<<<dim3(NPTS/128, OUTC/128),256>>>();
  k_fout <<<BB*OUTC/256,256>>>(gf, bf, out);
}